// round 5
// baseline (speedup 1.0000x reference)
#include <cuda_runtime.h>
#include <math.h>

// Fixed problem shapes
#define BB 8
#define CC 16
constexpr int HW    = 512 * 512;        // 262144 = 2^18
constexpr int NPIX  = BB * HW;          // 2097152
constexpr int NSEG  = BB * CC;          // 128
constexpr long long NTOT = (long long)NSEG * HW;  // 33554432
constexpr int NBIN  = 32768;            // error bins over e in [0,2]

// Static scratch (zero-init at load; self-cleaning across graph replays)
__device__ int    g_tot[NSEG * NBIN];   // 16 MB
__device__ int    g_posh[NSEG * NBIN];  // 16 MB
__device__ double g_bce;
__device__ double g_lov;
__device__ int    g_is32;               // 1 if target buffer is int32

// ---------------------------------------------------------------------------
__global__ void reset_flag_kernel() { g_is32 = 0; }

// Sample odd 32-bit words of the target buffer. Reading the first NPIX words
// is in-bounds whether the buffer holds NPIX int32 or NPIX int64 elements.
// int64 (values 0..16, LE) => every odd word is zero. int32 => values 0..16
// land at odd word positions; P(all 8192 samples zero) = (1/17)^8192 ~ 0.
__global__ void detect_kernel(const unsigned int* __restrict__ t) {
    int i = blockIdx.x * 256 + threadIdx.x;      // i < 8192 sampled pairs
    if (t[2 * i + 1] != 0u) atomicOr(&g_is32, 1);
}

// ---------------------------------------------------------------------------
// Pass A: per pixel over 16 channels — histogram errors, accumulate BCE.
__global__ void __launch_bounds__(256) passA_kernel(
    const float* __restrict__ logits,
    const void* __restrict__ target)
{
    int tid = threadIdx.x;
    int p   = blockIdx.x * 256 + tid;    // exact grid: p < NPIX
    int b   = p >> 18;                    // HW = 2^18
    int pix = p & (HW - 1);

    int is32 = g_is32;                    // uniform per launch
    long long tl = is32 ? (long long)((const int*)target)[p]
                        : ((const long long*)target)[p];
    int tc = (tl < (long long)CC) ? (int)tl : -1;   // -1 => ignored pixel

    float fsum = 0.0f;
    #pragma unroll
    for (int c = 0; c < CC; c++) {
        int seg = b * CC + c;
        float l = logits[(size_t)seg * HW + pix];
        int   y = (c == tc) ? 1 : 0;
        // e = 1 - tanh(l) (y=1) or 1 + tanh(l) (y=0)  ==  2 / (1 + exp(2*s*l))
        float s2l = y ? (2.0f * l) : (-2.0f * l);
        float e   = 2.0f / (1.0f + __expf(s2l));       // e in [0,2]
        int  ib = (int)(e * (0.5f * NBIN));
        ib = ib > (NBIN - 1) ? (NBIN - 1) : ib;
        atomicAdd(&g_tot[seg * NBIN + ib], 1);
        if (y) atomicAdd(&g_posh[seg * NBIN + ib], 1);

        if (tc >= 0) {
            // log p = -softplus(-l); log(1-p) = log p - l; clip at -100
            float al  = fabsf(l);
            float lp1 = __logf(1.0f + __expf(-al));
            float logp   = (l >= 0.0f) ? -lp1 : (l - lp1);
            float log1mp = logp - l;
            logp   = fmaxf(logp,   -100.0f);
            log1mp = fmaxf(log1mp, -100.0f);
            fsum += y ? -logp : -log1mp;
        }
    }

    // block reduce BCE partial -> one double atomic per block
    int lane = tid & 31, wid = tid >> 5;
    #pragma unroll
    for (int o = 16; o > 0; o >>= 1) fsum += __shfl_down_sync(0xffffffffu, fsum, o);
    __shared__ float wpart[8];
    if (lane == 0) wpart[wid] = fsum;
    __syncthreads();
    if (tid == 0) {
        double s = 0.0;
        #pragma unroll
        for (int i = 0; i < 8; i++) s += (double)wpart[i];
        atomicAdd(&g_bce, s);
    }
}

// ---------------------------------------------------------------------------
// Pass C: one block per segment. Walk bins in descending error order; a bin
// with P positives / Q negatives entering at prefix state (k,m) contributes
//   e_bin * [ (P+Q)(G+m) - Q(k+m) ] / [ (G+m)(G+m+Q) ]
// (exact telescoped Lovasz sum over a constant-error run; order within a bin
// provably cancels). Self-cleans the histogram for the next graph replay.
__global__ void __launch_bounds__(512) passC_kernel()
{
    constexpr int T = 512;
    int tid  = threadIdx.x;
    int lane = tid & 31, wid = tid >> 5;
    int seg  = blockIdx.x;
    int* tot = g_tot  + seg * NBIN;
    int* pos = g_posh + seg * NBIN;

    // ---- stage 1: G = total positives
    int gs = 0;
    for (int j = tid; j < NBIN; j += T) gs += pos[j];
    #pragma unroll
    for (int o = 16; o > 0; o >>= 1) gs += __shfl_down_sync(0xffffffffu, gs, o);
    __shared__ int wsumi[16];
    if (lane == 0) wsumi[wid] = gs;
    __syncthreads();
    __shared__ int sG;
    if (tid == 0) {
        int s = 0;
        #pragma unroll
        for (int i = 0; i < 16; i++) s += wsumi[i];
        sG = s;
    }
    __syncthreads();
    int G = sG;

    // ---- stage 2: descending bins, NBIN/T tiles
    __shared__ unsigned long long wscan[16];
    __shared__ int sK0, sM0;
    if (tid == 0) { sK0 = 0; sM0 = 0; }
    __syncthreads();

    double dacc = 0.0;

    for (int tile = 0; tile < NBIN / T; tile++) {
        int bin = NBIN - 1 - (tile * T + tid);
        int P   = pos[bin];
        int Q   = tot[bin] - P;
        pos[bin] = 0;                     // self-clean for next replay
        tot[bin] = 0;

        // inclusive block scan of packed (P<<32 | Q)
        unsigned long long v = ((unsigned long long)(unsigned)P << 32) | (unsigned)Q;
        unsigned long long x = v;
        #pragma unroll
        for (int o = 1; o < 32; o <<= 1) {
            unsigned long long yv = __shfl_up_sync(0xffffffffu, x, o);
            if (lane >= o) x += yv;
        }
        if (lane == 31) wscan[wid] = x;
        __syncthreads();
        if (wid == 0) {
            unsigned long long w = (lane < 16) ? wscan[lane] : 0ull;
            #pragma unroll
            for (int o = 1; o < 16; o <<= 1) {
                unsigned long long yv = __shfl_up_sync(0xffffffffu, w, o);
                if (lane >= o) w += yv;
            }
            if (lane < 16) wscan[lane] = w;
        }
        __syncthreads();
        unsigned long long incl = x + (wid ? wscan[wid - 1] : 0ull);
        unsigned long long excl = incl - v;

        int k = sK0 + (int)(excl >> 32);
        int m = sM0 + (int)(excl & 0xffffffffu);

        if ((P | Q) != 0) {
            int gm = G + m;
            double dj;
            if (gm == 0) {
                dj = 1.0;                 // G==0 corner: first nonempty bin
            } else {
                double num = (double)(P + Q) * (double)gm
                           - (double)Q * (double)(k + m);
                double den = (double)gm * (double)(gm + Q);
                dj = num / den;
            }
            float eb = ((float)bin + 0.5f) * (2.0f / NBIN);
            dacc += (double)eb * dj;
        }

        __syncthreads();
        if (tid == T - 1) {
            sK0 += (int)(incl >> 32);
            sM0 += (int)(incl & 0xffffffffu);
        }
        __syncthreads();
    }

    // block reduce doubles -> one atomic per segment
    #pragma unroll
    for (int o = 16; o > 0; o >>= 1) dacc += __shfl_down_sync(0xffffffffu, dacc, o);
    __shared__ double dsum[16];
    if (lane == 0) dsum[wid] = dacc;
    __syncthreads();
    if (tid == 0) {
        double s = 0.0;
        #pragma unroll
        for (int i = 0; i < 16; i++) s += dsum[i];
        atomicAdd(&g_lov, s);
    }
}

// ---------------------------------------------------------------------------
__global__ void final_kernel(float* out) {
    double lov = g_lov / (double)NSEG;    // mean over (b,c)
    double bce = g_bce / (double)NTOT;    // mean over all elements
    out[0] = (float)(lov + bce);          // ALPHA = 1
    g_lov = 0.0;                          // self-clean for replays
    g_bce = 0.0;
}

// ---------------------------------------------------------------------------
extern "C" void kernel_launch(void* const* d_in, const int* in_sizes, int n_in,
                              void* d_out, int out_size) {
    (void)n_in; (void)out_size;
    // Resolve input order by element counts (logits=33554432 >> target=2097152)
    int li = (in_sizes[0] > in_sizes[1]) ? 0 : 1;
    const float* logits = (const float*)d_in[li];
    const void*  target = d_in[1 - li];
    float*       out    = (float*)d_out;

    reset_flag_kernel<<<1, 1>>>();
    detect_kernel<<<32, 256>>>((const unsigned int*)target);
    passA_kernel<<<NPIX / 256, 256>>>(logits, target);
    passC_kernel<<<NSEG, 512>>>();
    final_kernel<<<1, 1>>>(out);
}